// round 9
// baseline (speedup 1.0000x reference)
#include <cuda_runtime.h>
#include <math.h>

// Problem constants
#define BATCH 4
#define NSEQ  4096
#define DIM   512
#define KH    64
#define MTOT  (BATCH*NSEQ)      // 16384
#define NCH   512               // prefix-scan chunks per batch
#define CHLEN (NSEQ/NCH)        // 8

typedef unsigned long long ull;

// packed fp32x2 helpers (sm_103a FFMA2 path)
#define FMA2(d, a, b) \
    asm("fma.rn.f32x2 %0, %1, %2, %0;" : "+l"(d) : "l"(a), "l"(b))
#define PACK2(out, f) \
    asm("mov.b64 %0, {%1, %1};" : "=l"(out) : "r"(__float_as_uint(f)))
#define UNPACK2(lo, hi, v) \
    do { unsigned int _l, _h; \
         asm("mov.b64 {%0, %1}, %2;" : "=r"(_l), "=r"(_h) : "l"(v)); \
         lo = __uint_as_float(_l); hi = __uint_as_float(_h); } while (0)

// ---------------- scratch (device globals) ------------------------------------------
__device__ __align__(16) float g_h[MTOT*KH];          // 4 MB projected feats
__device__ __align__(16) float g_wb[DIM];             // folded Wa^T Wb
__device__ __align__(16) float g_wc[DIM];             // folded Wa^T Wc
__device__ float g_t1[MTOT];
__device__ float g_t2[MTOT];
__device__ float g_t2s[BATCH][NSEQ];                  // t2 sorted descending
__device__ int   g_perm[BATCH][NSEQ];
__device__ __align__(16) float g_A[BATCH][NSEQ+1][KH];   // prefix of e1*h
__device__ __align__(16) float g_B[BATCH][NSEQ+1][KH];   // prefix of e2*h
__device__ float g_Z1[BATCH][NSEQ+1];
__device__ float g_Z2[BATCH][NSEQ+1];
// transposed chunk totals/offsets: contiguous along c for coalesced scan
__device__ __align__(16) float g_tot1[BATCH][KH][NCH];
__device__ __align__(16) float g_tot2[BATCH][KH][NCH];
__device__ __align__(16) float g_totz1[BATCH][NCH];
__device__ __align__(16) float g_totz2[BATCH][NCH];
__device__ __align__(16) float g_off1[BATCH][KH][NCH];
__device__ __align__(16) float g_off2[BATCH][KH][NCH];
__device__ __align__(16) float g_offz1[BATCH][NCH];
__device__ __align__(16) float g_offz2[BATCH][NCH];

// ---------------- K0a: fold weights: g_wb[d] = sum_k Wa[k][d]*Wb[k] ------------------
__global__ void k_fold(const float* __restrict__ Wa, const float* __restrict__ Wb,
                       const float* __restrict__ Wc) {
    int d = threadIdx.x;                  // 512 threads
    float sb = 0.f, sc = 0.f;
#pragma unroll 8
    for (int k = 0; k < KH; k++) {
        float w = Wa[(size_t)k*DIM + d];
        sb += w * Wb[k];
        sc += w * Wc[k];
    }
    g_wb[d] = sb;
    g_wc[d] = sc;
}

// ---------------- K0b: t1/t2 directly from x (one warp per row) ----------------------
__global__ void k_t12(const float* __restrict__ x,
                      const float* __restrict__ wb_bias,
                      const float* __restrict__ wc_bias) {
    int lane = threadIdx.x & 31;
    int warp = threadIdx.x >> 5;          // 4 warps/block
    int row  = blockIdx.x*4 + warp;
    const float4* xr  = reinterpret_cast<const float4*>(x + (size_t)row*DIM);
    const float4* wb4 = reinterpret_cast<const float4*>(g_wb);
    const float4* wc4 = reinterpret_cast<const float4*>(g_wc);
    float s1 = 0.f, s2 = 0.f;
#pragma unroll
    for (int i = 0; i < 4; i++) {
        float4 xv = xr[lane + 32*i];
        float4 bv = wb4[lane + 32*i];
        float4 cv = wc4[lane + 32*i];
        s1 += xv.x*bv.x + xv.y*bv.y + xv.z*bv.z + xv.w*bv.w;
        s2 += xv.x*cv.x + xv.y*cv.y + xv.z*cv.z + xv.w*cv.w;
    }
#pragma unroll
    for (int s = 16; s; s >>= 1) {
        s1 += __shfl_xor_sync(0xFFFFFFFFu, s1, s);
        s2 += __shfl_xor_sync(0xFFFFFFFFu, s2, s);
    }
    if (lane == 0) {
        g_t1[row] = s1 + wb_bias[0];
        g_t2[row] = s2 + wc_bias[0];
    }
}

// ---------------- K1: h = x @ Wa^T via packed f32x2, 512 threads, chunk 32 ----------
__global__ void __launch_bounds__(512, 1)
k_gemm(const float* __restrict__ x, const float* __restrict__ Wa) {
    __shared__ __align__(16) float Xs[32*132];   // [dd][m], padded 132 (16.9 KB)
    __shared__ __align__(16) float Ws[32*64];    // [dd][k]  (8 KB)
    const int t  = threadIdx.x;          // 0..511
    const int m0 = blockIdx.x * 128;
    const int tm = t >> 4;               // 0..31 -> rows tm*4..tm*4+3 (2 pairs)
    const int tk = t & 15;               // 0..15 -> cols tk*4..tk*4+3

    ull acc2[2][4];                      // [row-pair][col]
#pragma unroll
    for (int j = 0; j < 2; j++)
#pragma unroll
        for (int c = 0; c < 4; c++) acc2[j][c] = 0ull;

    for (int d0 = 0; d0 < DIM; d0 += 32) {
        // Xs: 128 rows x 32 d = 1024 float4; 2 per thread
#pragma unroll
        for (int l = 0; l < 2; l++) {
            int q  = t + l*512;
            int dg = q & 7;              // 8 float4 groups per row
            int m  = q >> 3;             // 0..127
            float4 v = *reinterpret_cast<const float4*>(x + (size_t)(m0+m)*DIM + d0 + dg*4);
            Xs[(dg*4+0)*132 + m] = v.x;
            Xs[(dg*4+1)*132 + m] = v.y;
            Xs[(dg*4+2)*132 + m] = v.z;
            Xs[(dg*4+3)*132 + m] = v.w;
        }
        // Ws: 64 k x 32 d = 512 float4; 1 per thread
        {
            int dg = t & 7;
            int k  = t >> 3;             // 0..63
            float4 v = *reinterpret_cast<const float4*>(Wa + (size_t)k*DIM + d0 + dg*4);
            Ws[(dg*4+0)*64 + k] = v.x;
            Ws[(dg*4+1)*64 + k] = v.y;
            Ws[(dg*4+2)*64 + k] = v.z;
            Ws[(dg*4+3)*64 + k] = v.w;
        }
        __syncthreads();
#pragma unroll
        for (int dd = 0; dd < 32; dd++) {
            ulonglong2 xa = *reinterpret_cast<const ulonglong2*>(Xs + dd*132 + tm*4);
            float4 wv = *reinterpret_cast<const float4*>(Ws + dd*64 + tk*4);
            ull wd[4];
            PACK2(wd[0], wv.x);
            PACK2(wd[1], wv.y);
            PACK2(wd[2], wv.z);
            PACK2(wd[3], wv.w);
#pragma unroll
            for (int c = 0; c < 4; c++) {
                FMA2(acc2[0][c], xa.x, wd[c]);
                FMA2(acc2[1][c], xa.y, wd[c]);
            }
        }
        __syncthreads();
    }

    float acclo[2][4], acchi[2][4];
#pragma unroll
    for (int j = 0; j < 2; j++)
#pragma unroll
        for (int c = 0; c < 4; c++)
            UNPACK2(acclo[j][c], acchi[j][c], acc2[j][c]);

#pragma unroll
    for (int j = 0; j < 2; j++) {
        int mlo = m0 + tm*4 + 2*j;
        *reinterpret_cast<float4*>(g_h + (size_t)mlo*KH + tk*4) =
            make_float4(acclo[j][0],acclo[j][1],acclo[j][2],acclo[j][3]);
        *reinterpret_cast<float4*>(g_h + (size_t)(mlo+1)*KH + tk*4) =
            make_float4(acchi[j][0],acchi[j][1],acchi[j][2],acchi[j][3]);
    }
}

// ---------------- K2: per-batch bitonic sort (packed u64, warp stages) ---------------
__device__ __forceinline__ unsigned int fmap(float f) {
    unsigned int u = __float_as_uint(f);
    return (u & 0x80000000u) ? ~u : (u | 0x80000000u);
}
__device__ __forceinline__ float funmap(unsigned int u) {
    u = (u & 0x80000000u) ? (u & 0x7FFFFFFFu) : ~u;
    return __uint_as_float(u);
}

__global__ void k_sort() {
    __shared__ unsigned long long sv[NSEQ];   // 32 KB
    int b = blockIdx.x, tid = threadIdx.x;    // 1024 threads
    for (int r = tid; r < NSEQ; r += 1024) {
        unsigned int u = fmap(g_t2[b*NSEQ + r]);
        sv[r] = ((unsigned long long)u << 32) | (unsigned int)r;
    }
    __syncthreads();
    int lane = tid & 31, warp = tid >> 5;
    for (int k = 2; k <= NSEQ; k <<= 1) {
        for (int s = k >> 1; s >= 32; s >>= 1) {
#pragma unroll 1
            for (int t = tid; t < NSEQ/2; t += 1024) {
                int i = ((t & ~(s-1)) << 1) | (t & (s-1));
                int j = i + s;
                bool desc = ((i & k) == 0);
                unsigned long long a = sv[i], c = sv[j];
                bool sw = desc ? (a < c) : (a > c);
                if (sw) { sv[i] = c; sv[j] = a; }
            }
            __syncthreads();
        }
        {
            int smax = ((k >> 1) < 32) ? (k >> 1) : 16;
#pragma unroll 1
            for (int g = warp; g < NSEQ/32; g += 32) {
                int i = g*32 + lane;
                unsigned long long val = sv[i];
                bool desc = ((i & k) == 0);
#pragma unroll 1
                for (int s = smax; s >= 1; s >>= 1) {
                    unsigned long long other = __shfl_xor_sync(0xFFFFFFFFu, val, s);
                    bool upper = (lane & s) != 0;
                    bool takeMax = (upper != desc);
                    bool otherBigger = (other > val);
                    val = (takeMax == otherBigger) ? other : val;
                }
                sv[i] = val;
            }
            __syncthreads();
        }
    }
    for (int r = tid; r < NSEQ; r += 1024) {
        unsigned long long pv = sv[r];
        g_t2s[b][r]  = funmap((unsigned int)(pv >> 32));
        g_perm[b][r] = (int)(pv & 0xFFFFFFFFu);
    }
}

// ---------------- K3a: per-chunk totals (exp on the fly, transposed output) ----------
__global__ void k_psum_a() {
    int b = blockIdx.x >> 9;              // NCH=512
    int c = blockIdx.x & 511;
    int k = threadIdx.x;                  // 64 threads
    int r0 = c * CHLEN;
    float m2 = g_t2s[b][0];
    float s1=0.f, s2=0.f, z1=0.f, z2=0.f;
#pragma unroll
    for (int r = r0; r < r0 + CHLEN; r++) {
        float tv = g_t2s[b][r] - m2;
        float e1 = expf(tv);
        float e2 = expf(0.2f*tv);
        int   j  = g_perm[b][r];
        float hv = g_h[((size_t)b*NSEQ + j)*KH + k];
        s1 += e1*hv;  s2 += e2*hv;
        z1 += e1;     z2 += e2;
    }
    g_tot1[b][k][c] = s1;  g_tot2[b][k][c] = s2;
    if (k == 0) { g_totz1[b][c] = z1; g_totz2[b][c] = z2; }
}

// ---------------- K3b: parallel exclusive scan (coalesced float4 loads) --------------
__global__ void k_scan() {
    int b = blockIdx.x >> 6, k = blockIdx.x & 63;
    int warp = threadIdx.x >> 5, lane = threadIdx.x & 31;
    if (warp == 0) {
        const float4* p1 = reinterpret_cast<const float4*>(&g_tot1[b][k][lane*16]);
        const float4* p2 = reinterpret_cast<const float4*>(&g_tot2[b][k][lane*16]);
        float v1[16], v2[16];
#pragma unroll
        for (int g = 0; g < 4; g++) {
            float4 a = p1[g], d = p2[g];
            v1[g*4+0]=a.x; v1[g*4+1]=a.y; v1[g*4+2]=a.z; v1[g*4+3]=a.w;
            v2[g*4+0]=d.x; v2[g*4+1]=d.y; v2[g*4+2]=d.z; v2[g*4+3]=d.w;
        }
        float t1 = 0.f, t2 = 0.f;
#pragma unroll
        for (int i = 0; i < 16; i++) {
            float a = v1[i], d = v2[i];
            v1[i] = t1; t1 += a;
            v2[i] = t2; t2 += d;
        }
        float e1 = t1, e2 = t2;
#pragma unroll
        for (int s = 1; s < 32; s <<= 1) {
            float o1 = __shfl_up_sync(0xFFFFFFFFu, e1, s);
            float o2 = __shfl_up_sync(0xFFFFFFFFu, e2, s);
            if (lane >= s) { e1 += o1; e2 += o2; }
        }
        e1 -= t1; e2 -= t2;
        float4* q1 = reinterpret_cast<float4*>(&g_off1[b][k][lane*16]);
        float4* q2 = reinterpret_cast<float4*>(&g_off2[b][k][lane*16]);
#pragma unroll
        for (int g = 0; g < 4; g++) {
            q1[g] = make_float4(e1+v1[g*4+0], e1+v1[g*4+1], e1+v1[g*4+2], e1+v1[g*4+3]);
            q2[g] = make_float4(e2+v2[g*4+0], e2+v2[g*4+1], e2+v2[g*4+2], e2+v2[g*4+3]);
        }
    } else if (k == 0) {
        float v1[16], v2[16];
        float t1 = 0.f, t2 = 0.f;
#pragma unroll
        for (int i = 0; i < 16; i++) {
            int c = lane*16 + i;
            float a = g_totz1[b][c];
            float d = g_totz2[b][c];
            v1[i] = t1; t1 += a;
            v2[i] = t2; t2 += d;
        }
        float e1 = t1, e2 = t2;
#pragma unroll
        for (int s = 1; s < 32; s <<= 1) {
            float o1 = __shfl_up_sync(0xFFFFFFFFu, e1, s);
            float o2 = __shfl_up_sync(0xFFFFFFFFu, e2, s);
            if (lane >= s) { e1 += o1; e2 += o2; }
        }
        e1 -= t1; e2 -= t2;
#pragma unroll
        for (int i = 0; i < 16; i++) {
            int c = lane*16 + i;
            g_offz1[b][c] = e1 + v1[i];
            g_offz2[b][c] = e2 + v2[i];
        }
    }
}

// ---------------- K3c: write full prefix arrays --------------------------------------
__global__ void k_psum_c() {
    int b = blockIdx.x >> 9;
    int c = blockIdx.x & 511;
    int k = threadIdx.x;
    int r0 = c * CHLEN;
    float m2 = g_t2s[b][0];
    float s1 = g_off1[b][k][c], s2 = g_off2[b][k][c];
    float z1 = g_offz1[b][c],   z2 = g_offz2[b][c];
    if (c == 0) {
        g_A[b][0][k] = 0.f;  g_B[b][0][k] = 0.f;
        if (k == 0) { g_Z1[b][0] = 0.f; g_Z2[b][0] = 0.f; }
    }
#pragma unroll
    for (int r = r0; r < r0 + CHLEN; r++) {
        float tv = g_t2s[b][r] - m2;
        float e1 = expf(tv);
        float e2 = expf(0.2f*tv);
        int   j  = g_perm[b][r];
        float hv = g_h[((size_t)b*NSEQ + j)*KH + k];
        s1 += e1*hv;  s2 += e2*hv;
        g_A[b][r+1][k] = s1;
        g_B[b][r+1][k] = s2;
        if (k == 0) {
            z1 += e1;  z2 += e2;
            g_Z1[b][r+1] = z1;
            g_Z2[b][r+1] = z2;
        }
    }
}

// ---------------- K4: per-row output, one warp per row, warp-parallel search ---------
__global__ void k_out(float* __restrict__ out, const float* __restrict__ bias) {
    int lane = threadIdx.x & 31;
    int warp = threadIdx.x >> 5;          // 8 warps -> 8 rows per block
    int row  = blockIdx.x*8 + warp;
    int b    = row >> 12;

    float t1v = g_t1[row];
    float m2  = g_t2s[b][0];
    float u   = t1v + m2;
    float M   = (u > 0.f) ? u : 0.2f*u;
    float c1  = expf(u - M);
    float c2  = expf(0.2f*u - M);
    float tau = -t1v;

    const float* t2s = g_t2s[b];
    unsigned int b0 = __ballot_sync(0xFFFFFFFFu, t2s[lane*128]      > tau);
    unsigned int b1 = __ballot_sync(0xFFFFFFFFu, t2s[lane*128 + 64] > tau);
    int count1 = __popc(b0) + __popc(b1);
    int base   = count1 ? (count1 - 1) * 64 : 0;
    unsigned int d0 = __ballot_sync(0xFFFFFFFFu, t2s[base + lane]      > tau);
    unsigned int d1 = __ballot_sync(0xFFFFFFFFu, t2s[base + 32 + lane] > tau);
    int p = base + __popc(d0) + __popc(d1);

    float Z1p   = g_Z1[b][p];
    float Z2p   = g_Z2[b][p];
    float Z2tot = g_Z2[b][NSEQ];
    float inv_den = 1.0f / (c1*Z1p + c2*(Z2tot - Z2p));

    const float* Ap   = g_A[b][p];
    const float* Bp   = g_B[b][p];
    const float* Btot = g_B[b][NSEQ];
#pragma unroll
    for (int h = 0; h < 2; h++) {
        int k = lane + h*32;
        float num = c1*Ap[k] + c2*(Btot[k] - Bp[k]);
        out[(size_t)row*KH + k] = num*inv_den + bias[k];
    }
}

// ---------------- stream/event objects (host-side, created at module load) -----------
struct ForkCtx {
    cudaStream_t s2;
    cudaEvent_t  evA, evB;
    ForkCtx() {
        cudaStreamCreateWithFlags(&s2, cudaStreamNonBlocking);
        cudaEventCreateWithFlags(&evA, cudaEventDisableTiming);
        cudaEventCreateWithFlags(&evB, cudaEventDisableTiming);
    }
};
static ForkCtx g_fork;

// ---------------- launch ---------------------------------------------------------------
extern "C" void kernel_launch(void* const* d_in, const int* in_sizes, int n_in,
                              void* d_out, int out_size) {
    const float* x       = (const float*)d_in[0];
    const float* Wa      = (const float*)d_in[1];
    const float* Wb      = (const float*)d_in[2];
    const float* wb_bias = (const float*)d_in[3];
    const float* Wc      = (const float*)d_in[4];
    const float* wc_bias = (const float*)d_in[5];
    const float* bias    = (const float*)d_in[6];
    float* out = (float*)d_out;

    // t1/t2 first (folded weights), then sort forks onto s2 while gemm runs
    k_fold<<<1, 512>>>(Wa, Wb, Wc);
    k_t12 <<<MTOT/4, 128>>>(x, wb_bias, wc_bias);
    cudaEventRecord(g_fork.evA, 0);
    cudaStreamWaitEvent(g_fork.s2, g_fork.evA, 0);
    k_sort<<<BATCH, 1024, 0, g_fork.s2>>>();
    cudaEventRecord(g_fork.evB, g_fork.s2);

    k_gemm<<<MTOT/128, 512>>>(x, Wa);          // concurrent with k_sort

    cudaStreamWaitEvent(0, g_fork.evB, 0);     // join
    k_psum_a<<<BATCH*NCH,  64>>>();
    k_scan  <<<BATCH*KH,   64>>>();
    k_psum_c<<<BATCH*NCH,  64>>>();
    k_out   <<<MTOT/8,   256>>>(out, bias);
}

// round 10
// speedup vs baseline: 1.4594x; 1.4594x over previous
#include <cuda_runtime.h>
#include <math.h>

// Problem constants
#define BATCH 4
#define NSEQ  4096
#define DIM   512
#define KH    64
#define MTOT  (BATCH*NSEQ)      // 16384
#define NCH   512               // prefix-scan chunks per batch
#define CHLEN (NSEQ/NCH)        // 8

typedef unsigned long long ull;

// packed fp32x2 helpers (sm_103a FFMA2 path)
#define FMA2(d, a, b) \
    asm("fma.rn.f32x2 %0, %1, %2, %0;" : "+l"(d) : "l"(a), "l"(b))
#define PACK2(out, f) \
    asm("mov.b64 %0, {%1, %1};" : "=l"(out) : "r"(__float_as_uint(f)))
#define UNPACK2(lo, hi, v) \
    do { unsigned int _l, _h; \
         asm("mov.b64 {%0, %1}, %2;" : "=r"(_l), "=r"(_h) : "l"(v)); \
         lo = __uint_as_float(_l); hi = __uint_as_float(_h); } while (0)

// ---------------- scratch (device globals) ------------------------------------------
__device__ __align__(16) float g_h[MTOT*KH];          // 4 MB projected feats
__device__ __align__(16) float g_wb[DIM];             // folded Wa^T Wb
__device__ __align__(16) float g_wc[DIM];             // folded Wa^T Wc
__device__ float g_t1[MTOT];
__device__ float g_t2[MTOT];
__device__ float g_t2s[BATCH][NSEQ];                  // t2 sorted descending
__device__ int   g_perm[BATCH][NSEQ];
__device__ __align__(16) float g_A[BATCH][NSEQ+1][KH];   // prefix of e1*h
__device__ __align__(16) float g_B[BATCH][NSEQ+1][KH];   // prefix of e2*h
__device__ float g_Z1[BATCH][NSEQ+1];
__device__ float g_Z2[BATCH][NSEQ+1];
// transposed chunk totals/offsets: contiguous along c for coalesced scan
__device__ __align__(16) float g_tot1[BATCH][KH][NCH];
__device__ __align__(16) float g_tot2[BATCH][KH][NCH];
__device__ __align__(16) float g_totz1[BATCH][NCH];
__device__ __align__(16) float g_totz2[BATCH][NCH];
__device__ __align__(16) float g_off1[BATCH][KH][NCH];
__device__ __align__(16) float g_off2[BATCH][KH][NCH];
__device__ __align__(16) float g_offz1[BATCH][NCH];
__device__ __align__(16) float g_offz2[BATCH][NCH];

// ---------------- K0a: fold weights: g_wb[d] = sum_k Wa[k][d]*Wb[k] ------------------
__global__ void k_fold(const float* __restrict__ Wa, const float* __restrict__ Wb,
                       const float* __restrict__ Wc) {
    int d = threadIdx.x;                  // 512 threads
    float sb = 0.f, sc = 0.f;
#pragma unroll 8
    for (int k = 0; k < KH; k++) {
        float w = Wa[(size_t)k*DIM + d];
        sb += w * Wb[k];
        sc += w * Wc[k];
    }
    g_wb[d] = sb;
    g_wc[d] = sc;
}

// ---------------- K0b: t1/t2 directly from x (one warp per row) ----------------------
__global__ void k_t12(const float* __restrict__ x,
                      const float* __restrict__ wb_bias,
                      const float* __restrict__ wc_bias) {
    int lane = threadIdx.x & 31;
    int warp = threadIdx.x >> 5;          // 4 warps/block
    int row  = blockIdx.x*4 + warp;
    const float4* xr  = reinterpret_cast<const float4*>(x + (size_t)row*DIM);
    const float4* wb4 = reinterpret_cast<const float4*>(g_wb);
    const float4* wc4 = reinterpret_cast<const float4*>(g_wc);
    float s1 = 0.f, s2 = 0.f;
#pragma unroll
    for (int i = 0; i < 4; i++) {
        float4 xv = xr[lane + 32*i];
        float4 bv = wb4[lane + 32*i];
        float4 cv = wc4[lane + 32*i];
        s1 += xv.x*bv.x + xv.y*bv.y + xv.z*bv.z + xv.w*bv.w;
        s2 += xv.x*cv.x + xv.y*cv.y + xv.z*cv.z + xv.w*cv.w;
    }
#pragma unroll
    for (int s = 16; s; s >>= 1) {
        s1 += __shfl_xor_sync(0xFFFFFFFFu, s1, s);
        s2 += __shfl_xor_sync(0xFFFFFFFFu, s2, s);
    }
    if (lane == 0) {
        g_t1[row] = s1 + wb_bias[0];
        g_t2[row] = s2 + wc_bias[0];
    }
}

// ---------------- K1: h = x @ Wa^T, f32x2, register double-buffered ------------------
__global__ void __launch_bounds__(256, 1)
k_gemm(const float* __restrict__ x, const float* __restrict__ Wa) {
    __shared__ __align__(16) float Xs[16*132];   // [dd][m], padded 132
    __shared__ __align__(16) float Ws[16*64];    // [dd][k]
    const int t  = threadIdx.x;          // 0..255
    const int m0 = blockIdx.x * 128;
    const int tm = t >> 4;               // rows tm*8..tm*8+7 (4 pairs)
    const int tk = t & 15;               // cols tk*4..tk*4+3

    // load indices (constant per thread)
    const int xdg0 = t & 3,        xm0i = t >> 2;          // l=0
    const int xdg1 = (t+256) & 3,  xm1i = (t+256) >> 2;    // l=1
    const int wdg  = t & 3,        wk   = t >> 2;
    const float* xp0 = x  + (size_t)(m0 + xm0i)*DIM + xdg0*4;
    const float* xp1 = x  + (size_t)(m0 + xm1i)*DIM + xdg1*4;
    const float* wp  = Wa + (size_t)wk*DIM + wdg*4;

    ull acc2[4][4];
#pragma unroll
    for (int j = 0; j < 4; j++)
#pragma unroll
        for (int c = 0; c < 4; c++) acc2[j][c] = 0ull;

    // prefetch chunk 0
    float4 rx0 = *reinterpret_cast<const float4*>(xp0);
    float4 rx1 = *reinterpret_cast<const float4*>(xp1);
    float4 rw  = *reinterpret_cast<const float4*>(wp);

    for (int d0 = 0; d0 < DIM; d0 += 16) {
        // store current chunk to smem
        Xs[(xdg0*4+0)*132 + xm0i] = rx0.x;
        Xs[(xdg0*4+1)*132 + xm0i] = rx0.y;
        Xs[(xdg0*4+2)*132 + xm0i] = rx0.z;
        Xs[(xdg0*4+3)*132 + xm0i] = rx0.w;
        Xs[(xdg1*4+0)*132 + xm1i] = rx1.x;
        Xs[(xdg1*4+1)*132 + xm1i] = rx1.y;
        Xs[(xdg1*4+2)*132 + xm1i] = rx1.z;
        Xs[(xdg1*4+3)*132 + xm1i] = rx1.w;
        Ws[(wdg*4+0)*64 + wk] = rw.x;
        Ws[(wdg*4+1)*64 + wk] = rw.y;
        Ws[(wdg*4+2)*64 + wk] = rw.z;
        Ws[(wdg*4+3)*64 + wk] = rw.w;
        __syncthreads();

        // issue next chunk's global loads (overlap with compute below)
        if (d0 + 16 < DIM) {
            rx0 = *reinterpret_cast<const float4*>(xp0 + d0 + 16);
            rx1 = *reinterpret_cast<const float4*>(xp1 + d0 + 16);
            rw  = *reinterpret_cast<const float4*>(wp  + d0 + 16);
        }

#pragma unroll
        for (int dd = 0; dd < 16; dd++) {
            ulonglong2 xa = *reinterpret_cast<const ulonglong2*>(Xs + dd*132 + tm*8);
            ulonglong2 xb = *reinterpret_cast<const ulonglong2*>(Xs + dd*132 + tm*8 + 4);
            float4 wv = *reinterpret_cast<const float4*>(Ws + dd*64 + tk*4);
            ull wd[4];
            PACK2(wd[0], wv.x);
            PACK2(wd[1], wv.y);
            PACK2(wd[2], wv.z);
            PACK2(wd[3], wv.w);
            ull xpq[4] = {xa.x, xa.y, xb.x, xb.y};
#pragma unroll
            for (int j = 0; j < 4; j++) {
                FMA2(acc2[j][0], xpq[j], wd[0]);
                FMA2(acc2[j][1], xpq[j], wd[1]);
                FMA2(acc2[j][2], xpq[j], wd[2]);
                FMA2(acc2[j][3], xpq[j], wd[3]);
            }
        }
        __syncthreads();
    }

    float acclo[4][4], acchi[4][4];
#pragma unroll
    for (int j = 0; j < 4; j++)
#pragma unroll
        for (int c = 0; c < 4; c++)
            UNPACK2(acclo[j][c], acchi[j][c], acc2[j][c]);

#pragma unroll
    for (int j = 0; j < 4; j++) {
        int mlo = m0 + tm*8 + 2*j;
        *reinterpret_cast<float4*>(g_h + (size_t)mlo*KH + tk*4) =
            make_float4(acclo[j][0],acclo[j][1],acclo[j][2],acclo[j][3]);
        *reinterpret_cast<float4*>(g_h + (size_t)(mlo+1)*KH + tk*4) =
            make_float4(acchi[j][0],acchi[j][1],acchi[j][2],acchi[j][3]);
    }
}

// ---------------- K2: per-batch bitonic sort (packed u64, warp stages) ---------------
__device__ __forceinline__ unsigned int fmap(float f) {
    unsigned int u = __float_as_uint(f);
    return (u & 0x80000000u) ? ~u : (u | 0x80000000u);
}
__device__ __forceinline__ float funmap(unsigned int u) {
    u = (u & 0x80000000u) ? (u & 0x7FFFFFFFu) : ~u;
    return __uint_as_float(u);
}

__global__ void k_sort() {
    __shared__ unsigned long long sv[NSEQ];   // 32 KB
    int b = blockIdx.x, tid = threadIdx.x;    // 1024 threads
    for (int r = tid; r < NSEQ; r += 1024) {
        unsigned int u = fmap(g_t2[b*NSEQ + r]);
        sv[r] = ((unsigned long long)u << 32) | (unsigned int)r;
    }
    __syncthreads();
    int lane = tid & 31, warp = tid >> 5;
    for (int k = 2; k <= NSEQ; k <<= 1) {
        for (int s = k >> 1; s >= 32; s >>= 1) {
#pragma unroll 1
            for (int t = tid; t < NSEQ/2; t += 1024) {
                int i = ((t & ~(s-1)) << 1) | (t & (s-1));
                int j = i + s;
                bool desc = ((i & k) == 0);
                unsigned long long a = sv[i], c = sv[j];
                bool sw = desc ? (a < c) : (a > c);
                if (sw) { sv[i] = c; sv[j] = a; }
            }
            __syncthreads();
        }
        {
            int smax = ((k >> 1) < 32) ? (k >> 1) : 16;
#pragma unroll 1
            for (int g = warp; g < NSEQ/32; g += 32) {
                int i = g*32 + lane;
                unsigned long long val = sv[i];
                bool desc = ((i & k) == 0);
#pragma unroll 1
                for (int s = smax; s >= 1; s >>= 1) {
                    unsigned long long other = __shfl_xor_sync(0xFFFFFFFFu, val, s);
                    bool upper = (lane & s) != 0;
                    bool takeMax = (upper != desc);
                    bool otherBigger = (other > val);
                    val = (takeMax == otherBigger) ? other : val;
                }
                sv[i] = val;
            }
            __syncthreads();
        }
    }
    for (int r = tid; r < NSEQ; r += 1024) {
        unsigned long long pv = sv[r];
        g_t2s[b][r]  = funmap((unsigned int)(pv >> 32));
        g_perm[b][r] = (int)(pv & 0xFFFFFFFFu);
    }
}

// ---------------- K3a: per-chunk totals (exp on the fly, transposed output) ----------
__global__ void k_psum_a() {
    int b = blockIdx.x >> 9;              // NCH=512
    int c = blockIdx.x & 511;
    int k = threadIdx.x;                  // 64 threads
    int r0 = c * CHLEN;
    float m2 = g_t2s[b][0];
    float s1=0.f, s2=0.f, z1=0.f, z2=0.f;
#pragma unroll
    for (int r = r0; r < r0 + CHLEN; r++) {
        float tv = g_t2s[b][r] - m2;
        float e1 = expf(tv);
        float e2 = expf(0.2f*tv);
        int   j  = g_perm[b][r];
        float hv = g_h[((size_t)b*NSEQ + j)*KH + k];
        s1 += e1*hv;  s2 += e2*hv;
        z1 += e1;     z2 += e2;
    }
    g_tot1[b][k][c] = s1;  g_tot2[b][k][c] = s2;
    if (k == 0) { g_totz1[b][c] = z1; g_totz2[b][c] = z2; }
}

// ---------------- K3b: parallel exclusive scan (coalesced float4 loads) --------------
__global__ void k_scan() {
    int b = blockIdx.x >> 6, k = blockIdx.x & 63;
    int warp = threadIdx.x >> 5, lane = threadIdx.x & 31;
    if (warp == 0) {
        const float4* p1 = reinterpret_cast<const float4*>(&g_tot1[b][k][lane*16]);
        const float4* p2 = reinterpret_cast<const float4*>(&g_tot2[b][k][lane*16]);
        float v1[16], v2[16];
#pragma unroll
        for (int g = 0; g < 4; g++) {
            float4 a = p1[g], d = p2[g];
            v1[g*4+0]=a.x; v1[g*4+1]=a.y; v1[g*4+2]=a.z; v1[g*4+3]=a.w;
            v2[g*4+0]=d.x; v2[g*4+1]=d.y; v2[g*4+2]=d.z; v2[g*4+3]=d.w;
        }
        float t1 = 0.f, t2 = 0.f;
#pragma unroll
        for (int i = 0; i < 16; i++) {
            float a = v1[i], d = v2[i];
            v1[i] = t1; t1 += a;
            v2[i] = t2; t2 += d;
        }
        float e1 = t1, e2 = t2;
#pragma unroll
        for (int s = 1; s < 32; s <<= 1) {
            float o1 = __shfl_up_sync(0xFFFFFFFFu, e1, s);
            float o2 = __shfl_up_sync(0xFFFFFFFFu, e2, s);
            if (lane >= s) { e1 += o1; e2 += o2; }
        }
        e1 -= t1; e2 -= t2;
        float4* q1 = reinterpret_cast<float4*>(&g_off1[b][k][lane*16]);
        float4* q2 = reinterpret_cast<float4*>(&g_off2[b][k][lane*16]);
#pragma unroll
        for (int g = 0; g < 4; g++) {
            q1[g] = make_float4(e1+v1[g*4+0], e1+v1[g*4+1], e1+v1[g*4+2], e1+v1[g*4+3]);
            q2[g] = make_float4(e2+v2[g*4+0], e2+v2[g*4+1], e2+v2[g*4+2], e2+v2[g*4+3]);
        }
    } else if (k == 0) {
        float v1[16], v2[16];
        float t1 = 0.f, t2 = 0.f;
#pragma unroll
        for (int i = 0; i < 16; i++) {
            int c = lane*16 + i;
            float a = g_totz1[b][c];
            float d = g_totz2[b][c];
            v1[i] = t1; t1 += a;
            v2[i] = t2; t2 += d;
        }
        float e1 = t1, e2 = t2;
#pragma unroll
        for (int s = 1; s < 32; s <<= 1) {
            float o1 = __shfl_up_sync(0xFFFFFFFFu, e1, s);
            float o2 = __shfl_up_sync(0xFFFFFFFFu, e2, s);
            if (lane >= s) { e1 += o1; e2 += o2; }
        }
        e1 -= t1; e2 -= t2;
#pragma unroll
        for (int i = 0; i < 16; i++) {
            int c = lane*16 + i;
            g_offz1[b][c] = e1 + v1[i];
            g_offz2[b][c] = e2 + v2[i];
        }
    }
}

// ---------------- K3c: write full prefix arrays --------------------------------------
__global__ void k_psum_c() {
    int b = blockIdx.x >> 9;
    int c = blockIdx.x & 511;
    int k = threadIdx.x;
    int r0 = c * CHLEN;
    float m2 = g_t2s[b][0];
    float s1 = g_off1[b][k][c], s2 = g_off2[b][k][c];
    float z1 = g_offz1[b][c],   z2 = g_offz2[b][c];
    if (c == 0) {
        g_A[b][0][k] = 0.f;  g_B[b][0][k] = 0.f;
        if (k == 0) { g_Z1[b][0] = 0.f; g_Z2[b][0] = 0.f; }
    }
#pragma unroll
    for (int r = r0; r < r0 + CHLEN; r++) {
        float tv = g_t2s[b][r] - m2;
        float e1 = expf(tv);
        float e2 = expf(0.2f*tv);
        int   j  = g_perm[b][r];
        float hv = g_h[((size_t)b*NSEQ + j)*KH + k];
        s1 += e1*hv;  s2 += e2*hv;
        g_A[b][r+1][k] = s1;
        g_B[b][r+1][k] = s2;
        if (k == 0) {
            z1 += e1;  z2 += e2;
            g_Z1[b][r+1] = z1;
            g_Z2[b][r+1] = z2;
        }
    }
}

// ---------------- K4: per-row output, one warp per row, warp-parallel search ---------
__global__ void k_out(float* __restrict__ out, const float* __restrict__ bias) {
    int lane = threadIdx.x & 31;
    int warp = threadIdx.x >> 5;          // 8 warps -> 8 rows per block
    int row  = blockIdx.x*8 + warp;
    int b    = row >> 12;

    float t1v = g_t1[row];
    float m2  = g_t2s[b][0];
    float u   = t1v + m2;
    float M   = (u > 0.f) ? u : 0.2f*u;
    float c1  = expf(u - M);
    float c2  = expf(0.2f*u - M);
    float tau = -t1v;

    const float* t2s = g_t2s[b];
    unsigned int b0 = __ballot_sync(0xFFFFFFFFu, t2s[lane*128]      > tau);
    unsigned int b1 = __ballot_sync(0xFFFFFFFFu, t2s[lane*128 + 64] > tau);
    int count1 = __popc(b0) + __popc(b1);
    int base   = count1 ? (count1 - 1) * 64 : 0;
    unsigned int d0 = __ballot_sync(0xFFFFFFFFu, t2s[base + lane]      > tau);
    unsigned int d1 = __ballot_sync(0xFFFFFFFFu, t2s[base + 32 + lane] > tau);
    int p = base + __popc(d0) + __popc(d1);

    float Z1p   = g_Z1[b][p];
    float Z2p   = g_Z2[b][p];
    float Z2tot = g_Z2[b][NSEQ];
    float inv_den = 1.0f / (c1*Z1p + c2*(Z2tot - Z2p));

    const float* Ap   = g_A[b][p];
    const float* Bp   = g_B[b][p];
    const float* Btot = g_B[b][NSEQ];
#pragma unroll
    for (int h = 0; h < 2; h++) {
        int k = lane + h*32;
        float num = c1*Ap[k] + c2*(Btot[k] - Bp[k]);
        out[(size_t)row*KH + k] = num*inv_den + bias[k];
    }
}

// ---------------- stream/event objects (host-side, created at module load) -----------
struct ForkCtx {
    cudaStream_t s2;
    cudaEvent_t  evA, evB;
    ForkCtx() {
        cudaStreamCreateWithFlags(&s2, cudaStreamNonBlocking);
        cudaEventCreateWithFlags(&evA, cudaEventDisableTiming);
        cudaEventCreateWithFlags(&evB, cudaEventDisableTiming);
    }
};
static ForkCtx g_fork;

// ---------------- launch ---------------------------------------------------------------
extern "C" void kernel_launch(void* const* d_in, const int* in_sizes, int n_in,
                              void* d_out, int out_size) {
    const float* x       = (const float*)d_in[0];
    const float* Wa      = (const float*)d_in[1];
    const float* Wb      = (const float*)d_in[2];
    const float* wb_bias = (const float*)d_in[3];
    const float* Wc      = (const float*)d_in[4];
    const float* wc_bias = (const float*)d_in[5];
    const float* bias    = (const float*)d_in[6];
    float* out = (float*)d_out;

    // t1/t2 first (folded weights), then sort forks onto s2 while gemm runs
    k_fold<<<1, 512>>>(Wa, Wb, Wc);
    k_t12 <<<MTOT/4, 128>>>(x, wb_bias, wc_bias);
    cudaEventRecord(g_fork.evA, 0);
    cudaStreamWaitEvent(g_fork.s2, g_fork.evA, 0);
    k_sort<<<BATCH, 1024, 0, g_fork.s2>>>();
    cudaEventRecord(g_fork.evB, g_fork.s2);

    k_gemm<<<MTOT/128, 256>>>(x, Wa);          // concurrent with k_sort

    cudaStreamWaitEvent(0, g_fork.evB, 0);     // join
    k_psum_a<<<BATCH*NCH,  64>>>();
    k_scan  <<<BATCH*KH,   64>>>();
    k_psum_c<<<BATCH*NCH,  64>>>();
    k_out   <<<MTOT/8,   256>>>(out, bias);
}